// round 5
// baseline (speedup 1.0000x reference)
#include <cuda_runtime.h>
#include <cuda_bf16.h>
#include <math.h>

// Shapes (fixed by the problem)
#define B_ 4
#define T_ 1024
#define C_ 1024
#define H_ 16
#define D_ 64
#define L3C (3 * C_)          // 3072
#define NPOS (2 * T_ - 1)     // 2047

// Scratch (allocation-free rule: __device__ globals)
__device__ float g_qkv[(size_t)B_ * T_ * L3C];   // (B*T, 3C) row-major
__device__ float g_attn[(size_t)B_ * T_ * C_];   // (B*T, C) row-major, C = h*64+d
__device__ float g_table[NPOS * H_];             // (2L-1, H)

// ---------------------------------------------------------------------------
// Kernel 1: reduce rel_pos_emb (2047,1024) -> table (2047,16) summing over D
// ---------------------------------------------------------------------------
__global__ __launch_bounds__(512) void reduce_table_kernel(const float* __restrict__ rel) {
    int row = blockIdx.x;           // 0..2046
    int w   = threadIdx.x >> 5;     // head 0..15
    int lane = threadIdx.x & 31;
    const float* p = rel + (size_t)row * C_ + w * D_;
    float s = p[lane] + p[lane + 32];
    #pragma unroll
    for (int off = 16; off > 0; off >>= 1)
        s += __shfl_xor_sync(0xffffffffu, s, off);
    if (lane == 0) g_table[row * H_ + w] = s;
}

// ---------------------------------------------------------------------------
// Kernel 2: SGEMM  C[M,N] = A[M,K] @ Bmat[N,K]^T + bias[N]
// BM=BN=64, BK=16, 256 threads, 4x4 per thread.
// ---------------------------------------------------------------------------
#define GBM 64
#define GBN 64
#define GBK 16
__global__ __launch_bounds__(256) void gemm_nt_bias(
    const float* __restrict__ A, const float* __restrict__ Bmat,
    const float* __restrict__ bias, float* __restrict__ Cout,
    int M, int N, int K)
{
    __shared__ float As[GBK][GBM + 4];   // [k][m]
    __shared__ float Bs[GBK][GBN + 4];

    const int tid = threadIdx.x;
    const int tx = tid & 15;
    const int ty = tid >> 4;
    const int m0 = blockIdx.y * GBM;
    const int n0 = blockIdx.x * GBN;

    const int lrow = tid >> 2;          // 0..63
    const int lcol = (tid & 3) * 4;     // 0,4,8,12

    float acc[4][4];
    #pragma unroll
    for (int i = 0; i < 4; i++)
        #pragma unroll
        for (int j = 0; j < 4; j++) acc[i][j] = 0.f;

    for (int k0 = 0; k0 < K; k0 += GBK) {
        float4 av = *(const float4*)&A[(size_t)(m0 + lrow) * K + k0 + lcol];
        float4 bv = *(const float4*)&Bmat[(size_t)(n0 + lrow) * K + k0 + lcol];
        As[lcol + 0][lrow] = av.x; As[lcol + 1][lrow] = av.y;
        As[lcol + 2][lrow] = av.z; As[lcol + 3][lrow] = av.w;
        Bs[lcol + 0][lrow] = bv.x; Bs[lcol + 1][lrow] = bv.y;
        Bs[lcol + 2][lrow] = bv.z; Bs[lcol + 3][lrow] = bv.w;
        __syncthreads();
        #pragma unroll
        for (int k = 0; k < GBK; k++) {
            float4 a4 = *(const float4*)&As[k][ty * 4];
            float4 b4 = *(const float4*)&Bs[k][tx * 4];
            float a[4] = {a4.x, a4.y, a4.z, a4.w};
            float b[4] = {b4.x, b4.y, b4.z, b4.w};
            #pragma unroll
            for (int i = 0; i < 4; i++)
                #pragma unroll
                for (int j = 0; j < 4; j++)
                    acc[i][j] = fmaf(a[i], b[j], acc[i][j]);
        }
        __syncthreads();
    }

    float bj[4];
    #pragma unroll
    for (int j = 0; j < 4; j++) bj[j] = bias[n0 + tx * 4 + j];
    #pragma unroll
    for (int i = 0; i < 4; i++) {
        float4 r;
        r.x = acc[i][0] + bj[0];
        r.y = acc[i][1] + bj[1];
        r.z = acc[i][2] + bj[2];
        r.w = acc[i][3] + bj[3];
        *(float4*)&Cout[(size_t)(m0 + ty * 4 + i) * N + n0 + tx * 4] = r;
    }
}

// ---------------------------------------------------------------------------
// Kernel 3: fused flash attention with rel-pos bias + causal mask.
// Grid: (T/64, B*H). Block: 256 threads (16x16), each thread 4x4.
// ---------------------------------------------------------------------------
#define QST_STRIDE 68
#define PS_STRIDE 65
// dynamic smem layout (floats):
//   Qst[64][68] | Kst[64][68] | Vs[64][64] | Ps[64][65] | sbias[128]
#define OFF_QST 0
#define OFF_KST (OFF_QST + 64 * QST_STRIDE)
#define OFF_VS  (OFF_KST + 64 * QST_STRIDE)
#define OFF_PS  (OFF_VS + 64 * 64)
#define OFF_SB  (OFF_PS + 64 * PS_STRIDE)
#define FLASH_SMEM_FLOATS (OFF_SB + 128)

__global__ __launch_bounds__(256) void flash_attn_kernel(float* __restrict__ out) {
    extern __shared__ float sm[];
    float* Qst   = sm + OFF_QST;   // [d][r] stride 68
    float* Kst   = sm + OFF_KST;   // [d][r] stride 68
    float* Vs    = sm + OFF_VS;    // [s][d] stride 64
    float* Ps    = sm + OFF_PS;    // [r][s] stride 65
    float* sbias = sm + OFF_SB;

    const int bh = blockIdx.y;
    const int b  = bh >> 4;
    const int h  = bh & 15;
    const int m0 = blockIdx.x * 64;

    const int tid = threadIdx.x;
    const int tx = tid & 15;
    const int ty = tid >> 4;
    const int lrow = tid >> 2;          // 0..63
    const int lcol = (tid & 3) * 4;     // 0,4,8,12 (stepped by +16 below -> full 64)

    // Load Q tile (transposed, pre-scaled by 1/sqrt(D)) — FULL 64 columns
    {
        const float sc = 0.125f;
        const float* qp = g_qkv + (size_t)(b * T_ + m0 + lrow) * L3C + h * D_;
        #pragma unroll
        for (int c = 0; c < 4; c++) {
            int col = lcol + c * 16;
            float4 v = *(const float4*)(qp + col);
            Qst[(col + 0) * QST_STRIDE + lrow] = v.x * sc;
            Qst[(col + 1) * QST_STRIDE + lrow] = v.y * sc;
            Qst[(col + 2) * QST_STRIDE + lrow] = v.z * sc;
            Qst[(col + 3) * QST_STRIDE + lrow] = v.w * sc;
        }
    }

    float m_i[4], l_i[4], o[4][4];
    #pragma unroll
    for (int i = 0; i < 4; i++) {
        m_i[i] = -1e30f; l_i[i] = 0.f;
        #pragma unroll
        for (int j = 0; j < 4; j++) o[i][j] = 0.f;
    }

    const int ntiles = blockIdx.x + 1;
    for (int t = 0; t < ntiles; t++) {
        const int j0 = t * 64;
        // load K tile (transposed) and V tile — FULL 64 columns each
        {
            const float* kp = g_qkv + (size_t)(b * T_ + j0 + lrow) * L3C + C_ + h * D_;
            const float* vp = g_qkv + (size_t)(b * T_ + j0 + lrow) * L3C + 2 * C_ + h * D_;
            #pragma unroll
            for (int c = 0; c < 4; c++) {
                int col = lcol + c * 16;
                float4 v = *(const float4*)(kp + col);
                Kst[(col + 0) * QST_STRIDE + lrow] = v.x;
                Kst[(col + 1) * QST_STRIDE + lrow] = v.y;
                Kst[(col + 2) * QST_STRIDE + lrow] = v.z;
                Kst[(col + 3) * QST_STRIDE + lrow] = v.w;
                *(float4*)&Vs[lrow * 64 + col] = *(const float4*)(vp + col);
            }
        }
        if (tid < 127) {
            // global rel index = (m0-j0) + (il-jl) + 1023 ; sidx = il-jl+63 in [0,126]
            sbias[tid] = g_table[(m0 - j0 + 960 + tid) * H_ + h];
        }
        __syncthreads();

        // S = Q K^T (scaled)
        float s[4][4];
        #pragma unroll
        for (int i = 0; i < 4; i++)
            #pragma unroll
            for (int j = 0; j < 4; j++) s[i][j] = 0.f;
        #pragma unroll 8
        for (int d = 0; d < 64; d++) {
            float4 a4 = *(const float4*)&Qst[d * QST_STRIDE + ty * 4];
            float4 b4 = *(const float4*)&Kst[d * QST_STRIDE + tx * 4];
            float a[4] = {a4.x, a4.y, a4.z, a4.w};
            float bb[4] = {b4.x, b4.y, b4.z, b4.w};
            #pragma unroll
            for (int i = 0; i < 4; i++)
                #pragma unroll
                for (int j = 0; j < 4; j++)
                    s[i][j] = fmaf(a[i], bb[j], s[i][j]);
        }
        // + bias, causal mask (only needed on diagonal tile)
        const bool diag = (t == blockIdx.x);
        #pragma unroll
        for (int i = 0; i < 4; i++) {
            int row = ty * 4 + i;
            #pragma unroll
            for (int j = 0; j < 4; j++) {
                int col = tx * 4 + j;
                s[i][j] += sbias[row - col + 63];
                if (diag && col > row) s[i][j] = -1e30f;
            }
        }
        // online softmax per row (reduce across the 16 tx lanes via xor shuffles)
        #pragma unroll
        for (int i = 0; i < 4; i++) {
            float mx = s[i][0];
            mx = fmaxf(mx, s[i][1]); mx = fmaxf(mx, s[i][2]); mx = fmaxf(mx, s[i][3]);
            #pragma unroll
            for (int off = 8; off > 0; off >>= 1)
                mx = fmaxf(mx, __shfl_xor_sync(0xffffffffu, mx, off));
            float mnew = fmaxf(m_i[i], mx);
            float corr = __expf(m_i[i] - mnew);
            float rs = 0.f;
            #pragma unroll
            for (int j = 0; j < 4; j++) {
                s[i][j] = __expf(s[i][j] - mnew);
                rs += s[i][j];
            }
            #pragma unroll
            for (int off = 8; off > 0; off >>= 1)
                rs += __shfl_xor_sync(0xffffffffu, rs, off);
            l_i[i] = l_i[i] * corr + rs;
            #pragma unroll
            for (int j = 0; j < 4; j++) o[i][j] *= corr;
            m_i[i] = mnew;
            // write P to shared
            int row = ty * 4 + i;
            #pragma unroll
            for (int j = 0; j < 4; j++)
                Ps[row * PS_STRIDE + tx * 4 + j] = s[i][j];
        }
        __syncthreads();

        // O += P @ V
        #pragma unroll 4
        for (int sI = 0; sI < 64; sI++) {
            float4 b4 = *(const float4*)&Vs[sI * 64 + tx * 4];
            float bb[4] = {b4.x, b4.y, b4.z, b4.w};
            float a0 = Ps[(ty * 4 + 0) * PS_STRIDE + sI];
            float a1 = Ps[(ty * 4 + 1) * PS_STRIDE + sI];
            float a2 = Ps[(ty * 4 + 2) * PS_STRIDE + sI];
            float a3 = Ps[(ty * 4 + 3) * PS_STRIDE + sI];
            #pragma unroll
            for (int j = 0; j < 4; j++) {
                o[0][j] = fmaf(a0, bb[j], o[0][j]);
                o[1][j] = fmaf(a1, bb[j], o[1][j]);
                o[2][j] = fmaf(a2, bb[j], o[2][j]);
                o[3][j] = fmaf(a3, bb[j], o[3][j]);
            }
        }
        __syncthreads();
    }

    // epilogue: normalize, write to (B,T,H*D)
    #pragma unroll
    for (int i = 0; i < 4; i++) {
        float inv = 1.f / l_i[i];
        int row = m0 + ty * 4 + i;
        float4 r;
        r.x = o[i][0] * inv; r.y = o[i][1] * inv;
        r.z = o[i][2] * inv; r.w = o[i][3] * inv;
        *(float4*)&out[(size_t)(b * T_ + row) * C_ + h * D_ + tx * 4] = r;
    }
}

// ---------------------------------------------------------------------------
extern "C" void kernel_launch(void* const* d_in, const int* in_sizes, int n_in,
                              void* d_out, int out_size) {
    const float* x      = (const float*)d_in[0];
    const float* qkv_w  = (const float*)d_in[1];
    const float* qkv_b  = (const float*)d_in[2];
    const float* proj_w = (const float*)d_in[3];
    const float* proj_b = (const float*)d_in[4];
    const float* rel    = (const float*)d_in[5];
    float* out = (float*)d_out;

    float *p_qkv, *p_attn;
    cudaGetSymbolAddress((void**)&p_qkv, g_qkv);
    cudaGetSymbolAddress((void**)&p_attn, g_attn);

    // 1) bias table reduce
    reduce_table_kernel<<<NPOS, 512>>>(rel);

    // 2) QKV projection: (4096,1024) @ (3072,1024)^T + b -> g_qkv
    {
        dim3 grid(L3C / GBN, (B_ * T_) / GBM);
        gemm_nt_bias<<<grid, 256>>>(x, qkv_w, qkv_b, p_qkv, B_ * T_, L3C, C_);
    }

    // 3) fused flash attention
    {
        static int smem_set = 0;
        size_t smem = FLASH_SMEM_FLOATS * sizeof(float);
        if (!smem_set) {
            cudaFuncSetAttribute(flash_attn_kernel,
                                 cudaFuncAttributeMaxDynamicSharedMemorySize, (int)smem);
            smem_set = 1;
        }
        dim3 grid(T_ / 64, B_ * H_);
        flash_attn_kernel<<<grid, 256, smem>>>(p_attn);
    }

    // 4) output projection: (4096,1024) @ (1024,1024)^T + b -> out
    {
        dim3 grid(C_ / GBN, (B_ * T_) / GBM);
        gemm_nt_bias<<<grid, 256>>>(p_attn, proj_w, proj_b, out, B_ * T_, C_, C_);
    }
}

// round 6
// speedup vs baseline: 1.4595x; 1.4595x over previous
#include <cuda_runtime.h>
#include <cuda_bf16.h>
#include <math.h>
#include <stdint.h>

// Shapes (fixed by the problem)
#define B_ 4
#define T_ 1024
#define C_ 1024
#define H_ 16
#define D_ 64
#define L3C (3 * C_)          // 3072
#define NPOS (2 * T_ - 1)     // 2047

// Scratch (allocation-free rule: __device__ globals)
__device__ float g_qkv[(size_t)B_ * T_ * L3C];   // (B*T, 3C) row-major
__device__ float g_attn[(size_t)B_ * T_ * C_];   // (B*T, C) row-major, C = h*64+d
__device__ float g_table[NPOS * H_];             // (2L-1, H)

// ---------------------------------------------------------------------------
// Kernel 1: reduce rel_pos_emb (2047,1024) -> table (2047,16) summing over D
// ---------------------------------------------------------------------------
__global__ __launch_bounds__(512) void reduce_table_kernel(const float* __restrict__ rel) {
    int row = blockIdx.x;           // 0..2046
    int w   = threadIdx.x >> 5;     // head 0..15
    int lane = threadIdx.x & 31;
    const float* p = rel + (size_t)row * C_ + w * D_;
    float s = p[lane] + p[lane + 32];
    #pragma unroll
    for (int off = 16; off > 0; off >>= 1)
        s += __shfl_xor_sync(0xffffffffu, s, off);
    if (lane == 0) g_table[row * H_ + w] = s;
}

// ---------------------------------------------------------------------------
// Kernel 2: TF32 tensor-core GEMM  C[M,N] = A[M,K] @ Bmat[N,K]^T + bias[N]
// 128x128x16 CTA tile, 256 threads, 8 warps (4m x 2n), warp tile 32x64,
// mma.sync.aligned.m16n8k8.row.col.f32.tf32.tf32.f32, double-buffered smem.
// ---------------------------------------------------------------------------
#define TBM 128
#define TBN 128
#define TBK 16
#define TST 136   // padded floats per k-row: conflict-free LDS & STS

__device__ __forceinline__ uint32_t f2tf32(float x) {
    uint32_t u;
    asm("cvt.rna.tf32.f32 %0, %1;" : "=r"(u) : "f"(x));
    return u;
}

__device__ __forceinline__ void mma_tf32(float* d, const uint32_t* a,
                                         uint32_t b0, uint32_t b1) {
    asm volatile(
        "mma.sync.aligned.m16n8k8.row.col.f32.tf32.tf32.f32 "
        "{%0,%1,%2,%3}, {%4,%5,%6,%7}, {%8,%9}, {%0,%1,%2,%3};\n"
        : "+f"(d[0]), "+f"(d[1]), "+f"(d[2]), "+f"(d[3])
        : "r"(a[0]), "r"(a[1]), "r"(a[2]), "r"(a[3]), "r"(b0), "r"(b1));
}

__global__ __launch_bounds__(256, 2) void gemm_tf32_nt_bias(
    const float* __restrict__ A, const float* __restrict__ Bm,
    const float* __restrict__ bias, float* __restrict__ Cout,
    int M, int N, int K)
{
    __shared__ float As[2][TBK][TST];
    __shared__ float Bs[2][TBK][TST];

    const int tid  = threadIdx.x;
    const int lane = tid & 31;
    const int wid  = tid >> 5;
    const int wm   = (wid & 3) * 32;   // warp m offset in tile
    const int wn   = (wid >> 2) * 64;  // warp n offset in tile
    const int m0   = blockIdx.y * TBM;
    const int n0   = blockIdx.x * TBN;

    const int qr = lane >> 2;   // quad row 0..7
    const int qc = lane & 3;    // quad col 0..3

    // loader: thread handles row (tid&127), k-quads {lh*2, lh*2+1}
    const int lr = tid & 127;
    const int lh = tid >> 7;    // 0/1

    const float* Aptr = A  + (size_t)(m0 + lr) * K + lh * 8;
    const float* Bptr = Bm + (size_t)(n0 + lr) * K + lh * 8;

    float acc[2][8][4];
    #pragma unroll
    for (int i = 0; i < 2; i++)
        #pragma unroll
        for (int j = 0; j < 8; j++)
            #pragma unroll
            for (int r = 0; r < 4; r++) acc[i][j][r] = 0.f;

    float4 fa[2], fb[2];
    // prefetch tile 0
    #pragma unroll
    for (int j = 0; j < 2; j++) {
        fa[j] = *(const float4*)(Aptr + j * 4);
        fb[j] = *(const float4*)(Bptr + j * 4);
    }
    // store tile 0
    #pragma unroll
    for (int j = 0; j < 2; j++) {
        int kk = lh * 8 + j * 4;
        As[0][kk + 0][lr] = __uint_as_float(f2tf32(fa[j].x));
        As[0][kk + 1][lr] = __uint_as_float(f2tf32(fa[j].y));
        As[0][kk + 2][lr] = __uint_as_float(f2tf32(fa[j].z));
        As[0][kk + 3][lr] = __uint_as_float(f2tf32(fa[j].w));
        Bs[0][kk + 0][lr] = __uint_as_float(f2tf32(fb[j].x));
        Bs[0][kk + 1][lr] = __uint_as_float(f2tf32(fb[j].y));
        Bs[0][kk + 2][lr] = __uint_as_float(f2tf32(fb[j].z));
        Bs[0][kk + 3][lr] = __uint_as_float(f2tf32(fb[j].w));
    }
    __syncthreads();

    const int nIter = K / TBK;
    for (int t = 0; t < nIter; t++) {
        const int buf = t & 1;
        if (t + 1 < nIter) {
            const float* ap = Aptr + (t + 1) * TBK;
            const float* bp = Bptr + (t + 1) * TBK;
            #pragma unroll
            for (int j = 0; j < 2; j++) {
                fa[j] = *(const float4*)(ap + j * 4);
                fb[j] = *(const float4*)(bp + j * 4);
            }
        }

        #pragma unroll
        for (int ks = 0; ks < 2; ks++) {
            const int kb = ks * 8;
            uint32_t af[2][4];
            #pragma unroll
            for (int ms = 0; ms < 2; ms++) {
                int r = wm + ms * 16 + qr;
                af[ms][0] = __float_as_uint(As[buf][kb + qc][r]);
                af[ms][1] = __float_as_uint(As[buf][kb + qc][r + 8]);
                af[ms][2] = __float_as_uint(As[buf][kb + qc + 4][r]);
                af[ms][3] = __float_as_uint(As[buf][kb + qc + 4][r + 8]);
            }
            #pragma unroll
            for (int ns = 0; ns < 8; ns++) {
                int c = wn + ns * 8 + qr;
                uint32_t b0 = __float_as_uint(Bs[buf][kb + qc][c]);
                uint32_t b1 = __float_as_uint(Bs[buf][kb + qc + 4][c]);
                mma_tf32(acc[0][ns], af[0], b0, b1);
                mma_tf32(acc[1][ns], af[1], b0, b1);
            }
        }

        if (t + 1 < nIter) {
            const int nb = buf ^ 1;
            #pragma unroll
            for (int j = 0; j < 2; j++) {
                int kk = lh * 8 + j * 4;
                As[nb][kk + 0][lr] = __uint_as_float(f2tf32(fa[j].x));
                As[nb][kk + 1][lr] = __uint_as_float(f2tf32(fa[j].y));
                As[nb][kk + 2][lr] = __uint_as_float(f2tf32(fa[j].z));
                As[nb][kk + 3][lr] = __uint_as_float(f2tf32(fa[j].w));
                Bs[nb][kk + 0][lr] = __uint_as_float(f2tf32(fb[j].x));
                Bs[nb][kk + 1][lr] = __uint_as_float(f2tf32(fb[j].y));
                Bs[nb][kk + 2][lr] = __uint_as_float(f2tf32(fb[j].z));
                Bs[nb][kk + 3][lr] = __uint_as_float(f2tf32(fb[j].w));
            }
        }
        __syncthreads();
    }

    // epilogue: + bias, write (float2 stores)
    #pragma unroll
    for (int ms = 0; ms < 2; ms++) {
        int r = m0 + wm + ms * 16 + qr;
        #pragma unroll
        for (int ns = 0; ns < 8; ns++) {
            int c = n0 + wn + ns * 8 + qc * 2;
            float b0 = bias[c], b1 = bias[c + 1];
            float2 v0 = make_float2(acc[ms][ns][0] + b0, acc[ms][ns][1] + b1);
            float2 v1 = make_float2(acc[ms][ns][2] + b0, acc[ms][ns][3] + b1);
            *(float2*)&Cout[(size_t)r * N + c]       = v0;
            *(float2*)&Cout[(size_t)(r + 8) * N + c] = v1;
        }
    }
}

// ---------------------------------------------------------------------------
// Kernel 3: fused flash attention with rel-pos bias + causal mask.
// Grid: (T/64, B*H). Block: 256 threads (16x16), each thread 4x4. (unchanged)
// ---------------------------------------------------------------------------
#define QST_STRIDE 68
#define PS_STRIDE 65
#define OFF_QST 0
#define OFF_KST (OFF_QST + 64 * QST_STRIDE)
#define OFF_VS  (OFF_KST + 64 * QST_STRIDE)
#define OFF_PS  (OFF_VS + 64 * 64)
#define OFF_SB  (OFF_PS + 64 * PS_STRIDE)
#define FLASH_SMEM_FLOATS (OFF_SB + 128)

__global__ __launch_bounds__(256) void flash_attn_kernel(float* __restrict__ out) {
    extern __shared__ float sm[];
    float* Qst   = sm + OFF_QST;
    float* Kst   = sm + OFF_KST;
    float* Vs    = sm + OFF_VS;
    float* Ps    = sm + OFF_PS;
    float* sbias = sm + OFF_SB;

    const int bh = blockIdx.y;
    const int b  = bh >> 4;
    const int h  = bh & 15;
    const int m0 = blockIdx.x * 64;

    const int tid = threadIdx.x;
    const int tx = tid & 15;
    const int ty = tid >> 4;
    const int lrow = tid >> 2;
    const int lcol = (tid & 3) * 4;

    {
        const float sc = 0.125f;
        const float* qp = g_qkv + (size_t)(b * T_ + m0 + lrow) * L3C + h * D_;
        #pragma unroll
        for (int c = 0; c < 4; c++) {
            int col = lcol + c * 16;
            float4 v = *(const float4*)(qp + col);
            Qst[(col + 0) * QST_STRIDE + lrow] = v.x * sc;
            Qst[(col + 1) * QST_STRIDE + lrow] = v.y * sc;
            Qst[(col + 2) * QST_STRIDE + lrow] = v.z * sc;
            Qst[(col + 3) * QST_STRIDE + lrow] = v.w * sc;
        }
    }

    float m_i[4], l_i[4], o[4][4];
    #pragma unroll
    for (int i = 0; i < 4; i++) {
        m_i[i] = -1e30f; l_i[i] = 0.f;
        #pragma unroll
        for (int j = 0; j < 4; j++) o[i][j] = 0.f;
    }

    const int ntiles = blockIdx.x + 1;
    for (int t = 0; t < ntiles; t++) {
        const int j0 = t * 64;
        {
            const float* kp = g_qkv + (size_t)(b * T_ + j0 + lrow) * L3C + C_ + h * D_;
            const float* vp = g_qkv + (size_t)(b * T_ + j0 + lrow) * L3C + 2 * C_ + h * D_;
            #pragma unroll
            for (int c = 0; c < 4; c++) {
                int col = lcol + c * 16;
                float4 v = *(const float4*)(kp + col);
                Kst[(col + 0) * QST_STRIDE + lrow] = v.x;
                Kst[(col + 1) * QST_STRIDE + lrow] = v.y;
                Kst[(col + 2) * QST_STRIDE + lrow] = v.z;
                Kst[(col + 3) * QST_STRIDE + lrow] = v.w;
                *(float4*)&Vs[lrow * 64 + col] = *(const float4*)(vp + col);
            }
        }
        if (tid < 127) {
            sbias[tid] = g_table[(m0 - j0 + 960 + tid) * H_ + h];
        }
        __syncthreads();

        float s[4][4];
        #pragma unroll
        for (int i = 0; i < 4; i++)
            #pragma unroll
            for (int j = 0; j < 4; j++) s[i][j] = 0.f;
        #pragma unroll 8
        for (int d = 0; d < 64; d++) {
            float4 a4 = *(const float4*)&Qst[d * QST_STRIDE + ty * 4];
            float4 b4 = *(const float4*)&Kst[d * QST_STRIDE + tx * 4];
            float a[4] = {a4.x, a4.y, a4.z, a4.w};
            float bb[4] = {b4.x, b4.y, b4.z, b4.w};
            #pragma unroll
            for (int i = 0; i < 4; i++)
                #pragma unroll
                for (int j = 0; j < 4; j++)
                    s[i][j] = fmaf(a[i], bb[j], s[i][j]);
        }
        const bool diag = (t == blockIdx.x);
        #pragma unroll
        for (int i = 0; i < 4; i++) {
            int row = ty * 4 + i;
            #pragma unroll
            for (int j = 0; j < 4; j++) {
                int col = tx * 4 + j;
                s[i][j] += sbias[row - col + 63];
                if (diag && col > row) s[i][j] = -1e30f;
            }
        }
        #pragma unroll
        for (int i = 0; i < 4; i++) {
            float mx = s[i][0];
            mx = fmaxf(mx, s[i][1]); mx = fmaxf(mx, s[i][2]); mx = fmaxf(mx, s[i][3]);
            #pragma unroll
            for (int off = 8; off > 0; off >>= 1)
                mx = fmaxf(mx, __shfl_xor_sync(0xffffffffu, mx, off));
            float mnew = fmaxf(m_i[i], mx);
            float corr = __expf(m_i[i] - mnew);
            float rs = 0.f;
            #pragma unroll
            for (int j = 0; j < 4; j++) {
                s[i][j] = __expf(s[i][j] - mnew);
                rs += s[i][j];
            }
            #pragma unroll
            for (int off = 8; off > 0; off >>= 1)
                rs += __shfl_xor_sync(0xffffffffu, rs, off);
            l_i[i] = l_i[i] * corr + rs;
            #pragma unroll
            for (int j = 0; j < 4; j++) o[i][j] *= corr;
            m_i[i] = mnew;
            int row = ty * 4 + i;
            #pragma unroll
            for (int j = 0; j < 4; j++)
                Ps[row * PS_STRIDE + tx * 4 + j] = s[i][j];
        }
        __syncthreads();

        #pragma unroll 4
        for (int sI = 0; sI < 64; sI++) {
            float4 b4 = *(const float4*)&Vs[sI * 64 + tx * 4];
            float bb[4] = {b4.x, b4.y, b4.z, b4.w};
            float a0 = Ps[(ty * 4 + 0) * PS_STRIDE + sI];
            float a1 = Ps[(ty * 4 + 1) * PS_STRIDE + sI];
            float a2 = Ps[(ty * 4 + 2) * PS_STRIDE + sI];
            float a3 = Ps[(ty * 4 + 3) * PS_STRIDE + sI];
            #pragma unroll
            for (int j = 0; j < 4; j++) {
                o[0][j] = fmaf(a0, bb[j], o[0][j]);
                o[1][j] = fmaf(a1, bb[j], o[1][j]);
                o[2][j] = fmaf(a2, bb[j], o[2][j]);
                o[3][j] = fmaf(a3, bb[j], o[3][j]);
            }
        }
        __syncthreads();
    }

    #pragma unroll
    for (int i = 0; i < 4; i++) {
        float inv = 1.f / l_i[i];
        int row = m0 + ty * 4 + i;
        float4 r;
        r.x = o[i][0] * inv; r.y = o[i][1] * inv;
        r.z = o[i][2] * inv; r.w = o[i][3] * inv;
        *(float4*)&out[(size_t)(b * T_ + row) * C_ + h * D_ + tx * 4] = r;
    }
}

// ---------------------------------------------------------------------------
extern "C" void kernel_launch(void* const* d_in, const int* in_sizes, int n_in,
                              void* d_out, int out_size) {
    const float* x      = (const float*)d_in[0];
    const float* qkv_w  = (const float*)d_in[1];
    const float* qkv_b  = (const float*)d_in[2];
    const float* proj_w = (const float*)d_in[3];
    const float* proj_b = (const float*)d_in[4];
    const float* rel    = (const float*)d_in[5];
    float* out = (float*)d_out;

    float *p_qkv, *p_attn;
    cudaGetSymbolAddress((void**)&p_qkv, g_qkv);
    cudaGetSymbolAddress((void**)&p_attn, g_attn);

    // 1) bias table reduce
    reduce_table_kernel<<<NPOS, 512>>>(rel);

    // 2) QKV projection: (4096,1024) @ (3072,1024)^T + b -> g_qkv  (tf32 MMA)
    {
        dim3 grid(L3C / TBN, (B_ * T_) / TBM);
        gemm_tf32_nt_bias<<<grid, 256>>>(x, qkv_w, qkv_b, p_qkv, B_ * T_, L3C, C_);
    }

    // 3) fused flash attention
    {
        static int smem_set = 0;
        size_t smem = FLASH_SMEM_FLOATS * sizeof(float);
        if (!smem_set) {
            cudaFuncSetAttribute(flash_attn_kernel,
                                 cudaFuncAttributeMaxDynamicSharedMemorySize, (int)smem);
            smem_set = 1;
        }
        dim3 grid(T_ / 64, B_ * H_);
        flash_attn_kernel<<<grid, 256, smem>>>(p_attn);
    }

    // 4) output projection: (4096,1024) @ (1024,1024)^T + b -> out  (tf32 MMA)
    {
        dim3 grid(C_ / TBN, (B_ * T_) / TBM);
        gemm_tf32_nt_bias<<<grid, 256>>>(p_attn, proj_w, proj_b, out, B_ * T_, C_, C_);
    }
}